// round 13
// baseline (speedup 1.0000x reference)
#include <cuda_runtime.h>
#include <cuda_bf16.h>
#include <cstdint>

// ---------------- problem constants ----------------
#define B_   8
#define H_   8
#define S_   1024
#define DH   64
#define D_   512
#define MR   8192                // B_*S_
#define NCH  16                  // 512 / 32
#define NSLOT (MR * D_)          // 4194304 activation elems
#define WSLOT (D_ * D_)          // 262144 weight elems

// ---------------- scratch (device globals; no allocation allowed) ---------
__device__ float g_q[B_ * H_ * S_ * DH];   // [BH,S,64], pre-scaled by 0.125
__device__ float g_k[B_ * H_ * S_ * DH];
__device__ float g_v[B_ * H_ * S_ * DH];
__device__ __align__(128) __nv_bfloat16 g_xh[3 * NSLOT];  // hi of query,key,value
__device__ __align__(128) __nv_bfloat16 g_xl[3 * NSLOT];  // lo residual
__device__ __align__(128) __nv_bfloat16 g_wh[4 * WSLOT];  // hi of Wq,Wk,Wv,Wo ([k][n])
__device__ __align__(128) __nv_bfloat16 g_wl[4 * WSLOT];
__device__ __align__(128) __nv_bfloat16 g_aoh[NSLOT];     // attn out hi [B*S,512]
__device__ __align__(128) __nv_bfloat16 g_aol[NSLOT];     // attn out lo

// ---------------- SMEM layout (bytes, per stage) ----------------
// Ah: 128 rows x 80B (32 bf16 + 16B pad)    = 10240
// Al: same                                    = 10240
// Bh: 32 k-rows x 272B (128 bf16 + 16B pad)  =  8704
// Bl: same                                    =  8704
#define AH_OFF  0
#define AL_OFF  10240
#define BH_OFF  20480
#define BL_OFF  29184
#define STAGE   37888
#define NSTAGE  3
#define SMEM_TOTAL (NSTAGE * STAGE)   // 113664 -> 2 CTAs/SM (227328 <= 227KB)

__device__ __forceinline__ uint32_t smem_u32(const void* p) {
    uint32_t a;
    asm("{ .reg .u64 t; cvta.to.shared.u64 t, %1; cvt.u32.u64 %0, t; }" : "=r"(a) : "l"(p));
    return a;
}

#define CP16(dst, src) \
    asm volatile("cp.async.cg.shared.global [%0], [%1], 16;" :: "r"(dst), "l"(src))
#define CP_COMMIT() asm volatile("cp.async.commit_group;" ::: "memory")
#define CP_WAIT2()  asm volatile("cp.async.wait_group 2;" ::: "memory")

#define LDSM4(r, addr) \
    asm volatile("ldmatrix.sync.aligned.m8n8.x4.shared.b16 {%0,%1,%2,%3}, [%4];" \
        : "=r"((r)[0]), "=r"((r)[1]), "=r"((r)[2]), "=r"((r)[3]) : "r"(addr))
#define LDSM4T(r, addr) \
    asm volatile("ldmatrix.sync.aligned.m8n8.x4.trans.shared.b16 {%0,%1,%2,%3}, [%4];" \
        : "=r"((r)[0]), "=r"((r)[1]), "=r"((r)[2]), "=r"((r)[3]) : "r"(addr))
#define MMA16816(c, a, b0, b1) \
    asm volatile("mma.sync.aligned.m16n8k16.row.col.f32.bf16.bf16.f32 " \
        "{%0,%1,%2,%3}, {%4,%5,%6,%7}, {%8,%9}, {%0,%1,%2,%3};" \
        : "+f"((c)[0]), "+f"((c)[1]), "+f"((c)[2]), "+f"((c)[3]) \
        : "r"((a)[0]), "r"((a)[1]), "r"((a)[2]), "r"((a)[3]), "r"(b0), "r"(b1))

// fp32 float4 -> packed hi (2x u32) and lo (2x u32)
__device__ __forceinline__ void split4(const float4 v, uint32_t& h01, uint32_t& h23,
                                       uint32_t& l01, uint32_t& l23) {
    __nv_bfloat16 h0 = __float2bfloat16_rn(v.x), h1 = __float2bfloat16_rn(v.y);
    __nv_bfloat16 h2 = __float2bfloat16_rn(v.z), h3 = __float2bfloat16_rn(v.w);
    __nv_bfloat162 H01(h0, h1), H23(h2, h3);
    __nv_bfloat162 L01(__float2bfloat16_rn(v.x - __bfloat162float(h0)),
                       __float2bfloat16_rn(v.y - __bfloat162float(h1)));
    __nv_bfloat162 L23(__float2bfloat16_rn(v.z - __bfloat162float(h2)),
                       __float2bfloat16_rn(v.w - __bfloat162float(h3)));
    h01 = *(uint32_t*)&H01; h23 = *(uint32_t*)&H23;
    l01 = *(uint32_t*)&L01; l23 = *(uint32_t*)&L23;
}

// ---------------------------------------------------------------------------
// prep kernels: split fp32 tensors into bf16 hi/lo pairs once per launch.
// ---------------------------------------------------------------------------
struct XArgs { const float* X[3]; };
struct WArgs { const float* W[4]; };

__global__ __launch_bounds__(256) void prep_x_kernel(XArgs xa) {
    const int z = blockIdx.y;
    const size_t i = (size_t)blockIdx.x * 256 + threadIdx.x;   // float4 idx
    const float4 v = ((const float4*)xa.X[z])[i];
    uint32_t h01, h23, l01, l23;
    split4(v, h01, h23, l01, l23);
    ((uint2*)(g_xh + (size_t)z * NSLOT))[i] = make_uint2(h01, h23);
    ((uint2*)(g_xl + (size_t)z * NSLOT))[i] = make_uint2(l01, l23);
}

__global__ __launch_bounds__(256) void prep_w_kernel(WArgs wa) {
    const int z = blockIdx.y;
    const size_t i = (size_t)blockIdx.x * 256 + threadIdx.x;
    const float4 v = ((const float4*)wa.W[z])[i];
    uint32_t h01, h23, l01, l23;
    split4(v, h01, h23, l01, l23);
    ((uint2*)(g_wh + (size_t)z * WSLOT))[i] = make_uint2(h01, h23);
    ((uint2*)(g_wl + (size_t)z * WSLOT))[i] = make_uint2(l01, l23);
}

// ---------------------------------------------------------------------------
// cp.async chunk loader: A[128 x 32] hi/lo + B[32 x 128] hi/lo (all bf16)
// ---------------------------------------------------------------------------
__device__ __forceinline__ void load_chunk(
    uint32_t sdst, const __nv_bfloat16* __restrict__ Ah,
    const __nv_bfloat16* __restrict__ Al, const __nv_bfloat16* __restrict__ Bh,
    const __nv_bfloat16* __restrict__ Bl, int rowBase, int colBase, int k0, int tid)
{
#pragma unroll
    for (int i = 0; i < 2; ++i) {
        const int idx = i * 256 + tid;
        // A: 512 16B units, 4 per 64B row
        const int row = idx >> 2, c4 = idx & 3;
        const size_t asrc = (size_t)(rowBase + row) * D_ + k0 + c4 * 8;
        const uint32_t ad = sdst + AH_OFF + row * 80 + c4 * 16;
        CP16(ad, Ah + asrc);
        CP16(ad + (AL_OFF - AH_OFF), Al + asrc);
        // B: 512 16B units, 16 per 256B row
        const int brow = idx >> 4, cc = idx & 15;
        const size_t bsrc = (size_t)(k0 + brow) * D_ + colBase + cc * 8;
        const uint32_t bd = sdst + BH_OFF + brow * 272 + cc * 16;
        CP16(bd, Bh + bsrc);
        CP16(bd + (BL_OFF - BH_OFF), Bl + bsrc);
    }
}

// ---------------------------------------------------------------------------
// bf16x3 compensated GEMM core, 3-stage cp.async pipeline.
// CTA tile 128(m) x 128(n), 8 warps of 64(m) x 32(n).
//   acc = (Ah+Al)[rowBase:+128,:] @ (Bh+Bl)[:, colBase:+128]
// Loads for chunk c+2 are issued at the TOP of iteration c, into the buffer
// freed after chunk c-1's compute — so a full chunk of MMA work covers the
// LDG latency instead of the post-compute serial tail (the 2-stage limiter).
// ---------------------------------------------------------------------------
__device__ __forceinline__ void gemm_core_mma(
    const __nv_bfloat16* __restrict__ Ah, const __nv_bfloat16* __restrict__ Al,
    const __nv_bfloat16* __restrict__ Bh, const __nv_bfloat16* __restrict__ Bl,
    int rowBase, int colBase, float (&acc)[4][4][4])
{
    extern __shared__ char smem[];
    const uint32_t sb = smem_u32(smem);
    const int tid  = threadIdx.x;
    const int wid  = tid >> 5, lane = tid & 31;
    const int wm   = wid >> 2, wn = wid & 3;
    const int lr   = lane & 15, lh = lane >> 4;

#pragma unroll
    for (int mi = 0; mi < 4; ++mi)
#pragma unroll
        for (int ni = 0; ni < 4; ++ni)
#pragma unroll
            for (int j = 0; j < 4; ++j) acc[mi][ni][j] = 0.0f;

    load_chunk(sb,         Ah, Al, Bh, Bl, rowBase, colBase, 0,  tid);
    CP_COMMIT();
    load_chunk(sb + STAGE, Ah, Al, Bh, Bl, rowBase, colBase, 32, tid);
    CP_COMMIT();

    int buf = 0, nbuf = 2;   // buffer holding chunk c; buffer to fill with c+2
    for (int c = 0; c < NCH; ++c) {
        // issue chunk c+2 into the buffer freed by chunk c-1's compute
        if (c + 2 < NCH)
            load_chunk(sb + (uint32_t)nbuf * STAGE, Ah, Al, Bh, Bl,
                       rowBase, colBase, (c + 2) * 32, tid);
        CP_COMMIT();            // unconditional: stable group numbering

        CP_WAIT2();             // chunk c complete (<=2 younger groups pending)
        __syncthreads();

        const uint32_t sbuf = sb + (uint32_t)buf * STAGE;
#pragma unroll
        for (int kh = 0; kh < 2; ++kh) {
            const int k16b = kh * 32;
            uint32_t bhf[2][4], blf[2][4];
#pragma unroll
            for (int nj = 0; nj < 2; ++nj) {
                const uint32_t baddr = sbuf + (uint32_t)(kh * 16 + lr) * 272
                                     + (uint32_t)(wn * 32 + nj * 16) * 2 + lh * 16;
                LDSM4T(bhf[nj], baddr + BH_OFF);
                LDSM4T(blf[nj], baddr + BL_OFF);
            }
#pragma unroll
            for (int mi = 0; mi < 4; ++mi) {
                uint32_t ah[4], al[4];
                const uint32_t raddr = sbuf + (uint32_t)(wm * 64 + mi * 16 + lr) * 80
                                     + k16b + lh * 16;
                LDSM4(ah, raddr + AH_OFF);
                LDSM4(al, raddr + AL_OFF);
#pragma unroll
                for (int ni = 0; ni < 4; ++ni) {
                    const int nj = ni >> 1, hp = (ni & 1) * 2;
                    MMA16816(acc[mi][ni], ah, bhf[nj][hp], bhf[nj][hp + 1]);
                }
#pragma unroll
                for (int ni = 0; ni < 4; ++ni) {
                    const int nj = ni >> 1, hp = (ni & 1) * 2;
                    MMA16816(acc[mi][ni], al, bhf[nj][hp], bhf[nj][hp + 1]);
                }
#pragma unroll
                for (int ni = 0; ni < 4; ++ni) {
                    const int nj = ni >> 1, hp = (ni & 1) * 2;
                    MMA16816(acc[mi][ni], ah, blf[nj][hp], blf[nj][hp + 1]);
                }
            }
        }
        __syncthreads();        // reads of buf done before it is refilled
        buf  = (buf == NSTAGE - 1) ? 0 : buf + 1;
        nbuf = (nbuf == NSTAGE - 1) ? 0 : nbuf + 1;
    }
}

// ---------------------------------------------------------------------------
// Q/K/V projection. z = blockIdx.z. Output head-split [B,H,S,64], Q x0.125.
// ---------------------------------------------------------------------------
struct BiasArgs { const float* bias[3]; };

__global__ __launch_bounds__(256, 2) void proj_mma_kernel(BiasArgs ba) {
    const int z = blockIdx.z;
    const int rowBase = blockIdx.y * 128;
    const int colBase = blockIdx.x * 128;

    float acc[4][4][4];
    gemm_core_mma(g_xh + (size_t)z * NSLOT, g_xl + (size_t)z * NSLOT,
                  g_wh + (size_t)z * WSLOT, g_wl + (size_t)z * WSLOT,
                  rowBase, colBase, acc);

    const int tid = threadIdx.x;
    const int wid = tid >> 5, lane = tid & 31;
    const int wm = wid >> 2, wn = wid & 3;
    const int g = lane >> 2, tq = lane & 3;

    float* dst = (z == 0) ? g_q : (z == 1) ? g_k : g_v;
    const float scale = (z == 0) ? 0.125f : 1.0f;
    const float* bias = ba.bias[z];

#pragma unroll
    for (int mi = 0; mi < 4; ++mi) {
        const int r0 = rowBase + wm * 64 + mi * 16 + g;
#pragma unroll
        for (int ni = 0; ni < 4; ++ni) {
            const int cc = colBase + wn * 32 + ni * 8 + tq * 2;
            const int h = cc >> 6, d = cc & 63;
            const float2 b2 = *(const float2*)(bias + cc);
            {
                const int r = r0, b = r >> 10, s = r & 1023;
                float* p = dst + ((size_t)((b * 8 + h) * 1024 + s)) * 64 + d;
                p[0] = (acc[mi][ni][0] + b2.x) * scale;
                p[1] = (acc[mi][ni][1] + b2.y) * scale;
            }
            {
                const int r = r0 + 8, b = r >> 10, s = r & 1023;
                float* p = dst + ((size_t)((b * 8 + h) * 1024 + s)) * 64 + d;
                p[0] = (acc[mi][ni][2] + b2.x) * scale;
                p[1] = (acc[mi][ni][3] + b2.y) * scale;
            }
        }
    }
}

// ---------------------------------------------------------------------------
// Final projection: d_out = (aoh+aol) @ Wo + bo
// ---------------------------------------------------------------------------
__global__ __launch_bounds__(256, 2) void out_mma_kernel(const float* __restrict__ bo,
                                                         float* __restrict__ out) {
    const int rowBase = blockIdx.y * 128;
    const int colBase = blockIdx.x * 128;

    float acc[4][4][4];
    gemm_core_mma(g_aoh, g_aol, g_wh + (size_t)3 * WSLOT, g_wl + (size_t)3 * WSLOT,
                  rowBase, colBase, acc);

    const int tid = threadIdx.x;
    const int wid = tid >> 5, lane = tid & 31;
    const int wm = wid >> 2, wn = wid & 3;
    const int g = lane >> 2, tq = lane & 3;

#pragma unroll
    for (int mi = 0; mi < 4; ++mi) {
        const int r0 = rowBase + wm * 64 + mi * 16 + g;
#pragma unroll
        for (int ni = 0; ni < 4; ++ni) {
            const int cc = colBase + wn * 32 + ni * 8 + tq * 2;
            const float2 b2 = *(const float2*)(bo + cc);
            {
                float* p = out + (size_t)r0 * D_ + cc;
                p[0] = acc[mi][ni][0] + b2.x;
                p[1] = acc[mi][ni][1] + b2.y;
            }
            {
                float* p = out + (size_t)(r0 + 8) * D_ + cc;
                p[0] = acc[mi][ni][2] + b2.x;
                p[1] = acc[mi][ni][3] + b2.y;
            }
        }
    }
}

// ---------------------------------------------------------------------------
// Sparse attention (champion, unchanged): one warp per (bh, query i);
// HALF-WARP per candidate. 34 candidates = 17 iterations x 2 halves.
// Writes bf16 hi/lo attn output directly.
// ---------------------------------------------------------------------------
__global__ __launch_bounds__(256) void attn_kernel() {
    const int gw   = (blockIdx.x * blockDim.x + threadIdx.x) >> 5;
    const int lane = threadIdx.x & 31;
    const int h2 = lane >> 4, sl = lane & 15;
    const int bh = gw >> 10;
    const int i  = gw & 1023;

    const float4* K4 = (const float4*)(g_k + (size_t)bh * (S_ * DH));
    const float4* V4 = (const float4*)(g_v + (size_t)bh * (S_ * DH));
    const float4 q = ((const float4*)(g_q + (size_t)gw * 64))[sl];

    const int t  = i >> 8;
    const int hh = (i >> 4) & 15;

    float lg[17];
    int   jc[17];
#pragma unroll
    for (int it = 0; it < 17; ++it) {
        const int c = it * 2 + h2;
        int j; bool valid;
        if (c < 17)      { j = i - 16 + c;              valid = (j >= 0); }
        else if (c < 31) { const int kk = c - 15; j = i - (kk << 4); valid = (kk <= hh); }
        else             { const int kk = c - 30; j = i - (kk << 8); valid = (kk <= t); }
        jc[it] = valid ? j : i;           // clamp to self row; masked below
        const float4 kv = K4[jc[it] * 16 + sl];
        float p = q.x * kv.x + q.y * kv.y + q.z * kv.z + q.w * kv.w;
        p += __shfl_xor_sync(0xffffffffu, p, 8);
        p += __shfl_xor_sync(0xffffffffu, p, 4);
        p += __shfl_xor_sync(0xffffffffu, p, 2);
        p += __shfl_xor_sync(0xffffffffu, p, 1);
        lg[it] = valid ? p : -1e30f;
    }

    float mx = -1e30f;
#pragma unroll
    for (int it = 0; it < 17; ++it) mx = fmaxf(mx, lg[it]);
    mx = fmaxf(mx, __shfl_xor_sync(0xffffffffu, mx, 16));

    float s = 0.0f;
#pragma unroll
    for (int it = 0; it < 17; ++it) {
        const float e = __expf(lg[it] - mx);   // invalid underflows to 0
        lg[it] = e;
        s += e;
    }
    s += __shfl_xor_sync(0xffffffffu, s, 16);

    float4 o = make_float4(0.f, 0.f, 0.f, 0.f);
#pragma unroll
    for (int it = 0; it < 17; ++it) {
        const float4 v = V4[jc[it] * 16 + sl];
        const float w = lg[it];
        o.x = fmaf(w, v.x, o.x);
        o.y = fmaf(w, v.y, o.y);
        o.z = fmaf(w, v.z, o.z);
        o.w = fmaf(w, v.w, o.w);
    }
    o.x += __shfl_xor_sync(0xffffffffu, o.x, 16);
    o.y += __shfl_xor_sync(0xffffffffu, o.y, 16);
    o.z += __shfl_xor_sync(0xffffffffu, o.z, 16);
    o.w += __shfl_xor_sync(0xffffffffu, o.w, 16);

    const float inv = 1.0f / s;
    o.x *= inv; o.y *= inv; o.z *= inv; o.w *= inv;

    // split to bf16 hi/lo; half 0 writes hi, half 1 writes lo
    uint32_t h01, h23, l01, l23;
    split4(o, h01, h23, l01, l23);
    const int b = bh >> 3, h = bh & 7;
    const size_t off = ((size_t)((b << 10) + i)) * 512 + (h << 6) + sl * 4;
    if (h2 == 0) *(uint2*)(g_aoh + off) = make_uint2(h01, h23);
    else         *(uint2*)(g_aol + off) = make_uint2(l01, l23);
}

// ---------------------------------------------------------------------------
extern "C" void kernel_launch(void* const* d_in, const int* in_sizes, int n_in,
                              void* d_out, int out_size) {
    const float* query = (const float*)d_in[0];
    const float* key   = (const float*)d_in[1];
    const float* value = (const float*)d_in[2];
    const float* Wq    = (const float*)d_in[3];
    const float* bq    = (const float*)d_in[4];
    const float* Wk    = (const float*)d_in[5];
    const float* bk    = (const float*)d_in[6];
    const float* Wv    = (const float*)d_in[7];
    const float* bv    = (const float*)d_in[8];
    const float* Wo    = (const float*)d_in[9];
    const float* bo    = (const float*)d_in[10];

    cudaFuncSetAttribute(proj_mma_kernel,
                         cudaFuncAttributeMaxDynamicSharedMemorySize, SMEM_TOTAL);
    cudaFuncSetAttribute(out_mma_kernel,
                         cudaFuncAttributeMaxDynamicSharedMemorySize, SMEM_TOTAL);

    WArgs wa; wa.W[0] = Wq; wa.W[1] = Wk; wa.W[2] = Wv; wa.W[3] = Wo;
    prep_w_kernel<<<dim3(256, 4), 256>>>(wa);

    XArgs xa; xa.X[0] = query; xa.X[1] = key; xa.X[2] = value;
    prep_x_kernel<<<dim3(4096, 3), 256>>>(xa);

    BiasArgs ba; ba.bias[0] = bq; ba.bias[1] = bk; ba.bias[2] = bv;
    proj_mma_kernel<<<dim3(4, 64, 3), 256, SMEM_TOTAL>>>(ba);

    attn_kernel<<<(B_ * H_ * S_ * 32) / 256, 256>>>();

    out_mma_kernel<<<dim3(4, 64, 1), 256, SMEM_TOTAL>>>(bo, (float*)d_out);
}

// round 15
// speedup vs baseline: 1.0051x; 1.0051x over previous
#include <cuda_runtime.h>
#include <cuda_bf16.h>
#include <cstdint>

// ---------------- problem constants ----------------
#define B_   8
#define H_   8
#define S_   1024
#define DH   64
#define D_   512
#define MR   8192                // B_*S_
#define NCH  16                  // 512 / 32
#define NSLOT (MR * D_)          // 4194304 activation elems
#define WSLOT (D_ * D_)          // 262144 weight elems

// ---------------- scratch (device globals; no allocation allowed) ---------
__device__ float g_q[B_ * H_ * S_ * DH];   // [BH,S,64], pre-scaled by 0.125
__device__ float g_k[B_ * H_ * S_ * DH];
__device__ float g_v[B_ * H_ * S_ * DH];
__device__ __align__(128) __nv_bfloat16 g_xh[3 * NSLOT];  // hi of query,key,value
__device__ __align__(128) __nv_bfloat16 g_xl[3 * NSLOT];  // lo residual
__device__ __align__(128) __nv_bfloat16 g_wh[4 * WSLOT];  // hi of Wq,Wk,Wv,Wo ([k][n])
__device__ __align__(128) __nv_bfloat16 g_wl[4 * WSLOT];
__device__ __align__(128) __nv_bfloat16 g_aoh[NSLOT];     // attn out hi [B*S,512]
__device__ __align__(128) __nv_bfloat16 g_aol[NSLOT];     // attn out lo

// ---------------- SMEM layout (bytes, per stage) ----------------
// Ah: 128 rows x 80B (32 bf16 + 16B pad)    = 10240
// Al: same                                    = 10240
// Bh: 32 k-rows x 272B (128 bf16 + 16B pad)  =  8704
// Bl: same                                    =  8704
#define AH_OFF  0
#define AL_OFF  10240
#define BH_OFF  20480
#define BL_OFF  29184
#define STAGE   37888
#define SMEM_TOTAL (2 * STAGE)   // 75776 -> 2 CTAs/SM

__device__ __forceinline__ uint32_t smem_u32(const void* p) {
    uint32_t a;
    asm("{ .reg .u64 t; cvta.to.shared.u64 t, %1; cvt.u32.u64 %0, t; }" : "=r"(a) : "l"(p));
    return a;
}

#define CP16(dst, src) \
    asm volatile("cp.async.cg.shared.global [%0], [%1], 16;" :: "r"(dst), "l"(src))
#define CP_COMMIT() asm volatile("cp.async.commit_group;" ::: "memory")
#define CP_WAIT1()  asm volatile("cp.async.wait_group 1;" ::: "memory")

#define LDSM4(r, addr) \
    asm volatile("ldmatrix.sync.aligned.m8n8.x4.shared.b16 {%0,%1,%2,%3}, [%4];" \
        : "=r"((r)[0]), "=r"((r)[1]), "=r"((r)[2]), "=r"((r)[3]) : "r"(addr))
#define LDSM4T(r, addr) \
    asm volatile("ldmatrix.sync.aligned.m8n8.x4.trans.shared.b16 {%0,%1,%2,%3}, [%4];" \
        : "=r"((r)[0]), "=r"((r)[1]), "=r"((r)[2]), "=r"((r)[3]) : "r"(addr))
#define MMA16816(c, a, b0, b1) \
    asm volatile("mma.sync.aligned.m16n8k16.row.col.f32.bf16.bf16.f32 " \
        "{%0,%1,%2,%3}, {%4,%5,%6,%7}, {%8,%9}, {%0,%1,%2,%3};" \
        : "+f"((c)[0]), "+f"((c)[1]), "+f"((c)[2]), "+f"((c)[3]) \
        : "r"((a)[0]), "r"((a)[1]), "r"((a)[2]), "r"((a)[3]), "r"(b0), "r"(b1))

// fp32 float4 -> packed hi (2x u32) and lo (2x u32)
__device__ __forceinline__ void split4(const float4 v, uint32_t& h01, uint32_t& h23,
                                       uint32_t& l01, uint32_t& l23) {
    __nv_bfloat16 h0 = __float2bfloat16_rn(v.x), h1 = __float2bfloat16_rn(v.y);
    __nv_bfloat16 h2 = __float2bfloat16_rn(v.z), h3 = __float2bfloat16_rn(v.w);
    __nv_bfloat162 H01(h0, h1), H23(h2, h3);
    __nv_bfloat162 L01(__float2bfloat16_rn(v.x - __bfloat162float(h0)),
                       __float2bfloat16_rn(v.y - __bfloat162float(h1)));
    __nv_bfloat162 L23(__float2bfloat16_rn(v.z - __bfloat162float(h2)),
                       __float2bfloat16_rn(v.w - __bfloat162float(h3)));
    h01 = *(uint32_t*)&H01; h23 = *(uint32_t*)&H23;
    l01 = *(uint32_t*)&L01; l23 = *(uint32_t*)&L23;
}

// ---------------------------------------------------------------------------
// prep kernels: split fp32 tensors into bf16 hi/lo pairs once per launch.
// ---------------------------------------------------------------------------
struct XArgs { const float* X[3]; };
struct WArgs { const float* W[4]; };

__global__ __launch_bounds__(256) void prep_x_kernel(XArgs xa) {
    const int z = blockIdx.y;
    const size_t i = (size_t)blockIdx.x * 256 + threadIdx.x;   // float4 idx
    const float4 v = ((const float4*)xa.X[z])[i];
    uint32_t h01, h23, l01, l23;
    split4(v, h01, h23, l01, l23);
    ((uint2*)(g_xh + (size_t)z * NSLOT))[i] = make_uint2(h01, h23);
    ((uint2*)(g_xl + (size_t)z * NSLOT))[i] = make_uint2(l01, l23);
}

__global__ __launch_bounds__(256) void prep_w_kernel(WArgs wa) {
    const int z = blockIdx.y;
    const size_t i = (size_t)blockIdx.x * 256 + threadIdx.x;
    const float4 v = ((const float4*)wa.W[z])[i];
    uint32_t h01, h23, l01, l23;
    split4(v, h01, h23, l01, l23);
    ((uint2*)(g_wh + (size_t)z * WSLOT))[i] = make_uint2(h01, h23);
    ((uint2*)(g_wl + (size_t)z * WSLOT))[i] = make_uint2(l01, l23);
}

// ---------------------------------------------------------------------------
// cp.async chunk loader: A[128 x 32] hi/lo + B[32 x 128] hi/lo (all bf16)
// ---------------------------------------------------------------------------
__device__ __forceinline__ void load_chunk(
    uint32_t sdst, const __nv_bfloat16* __restrict__ Ah,
    const __nv_bfloat16* __restrict__ Al, const __nv_bfloat16* __restrict__ Bh,
    const __nv_bfloat16* __restrict__ Bl, int rowBase, int colBase, int k0, int tid)
{
#pragma unroll
    for (int i = 0; i < 2; ++i) {
        const int idx = i * 256 + tid;
        // A: 512 16B units, 4 per 64B row
        const int row = idx >> 2, c4 = idx & 3;
        const size_t asrc = (size_t)(rowBase + row) * D_ + k0 + c4 * 8;
        const uint32_t ad = sdst + AH_OFF + row * 80 + c4 * 16;
        CP16(ad, Ah + asrc);
        CP16(ad + (AL_OFF - AH_OFF), Al + asrc);
        // B: 512 16B units, 16 per 256B row
        const int brow = idx >> 4, cc = idx & 15;
        const size_t bsrc = (size_t)(k0 + brow) * D_ + colBase + cc * 8;
        const uint32_t bd = sdst + BH_OFF + brow * 272 + cc * 16;
        CP16(bd, Bh + bsrc);
        CP16(bd + (BL_OFF - BH_OFF), Bl + bsrc);
    }
}

// ---------------------------------------------------------------------------
// bf16x3 compensated GEMM core (champion: 2-stage cp.async pipeline).
// CTA tile 128(m) x 128(n), 8 warps of 64(m) x 32(n).
//   acc = (Ah+Al)[rowBase:+128,:] @ (Bh+Bl)[:, colBase:+128]
// ---------------------------------------------------------------------------
__device__ __forceinline__ void gemm_core_mma(
    const __nv_bfloat16* __restrict__ Ah, const __nv_bfloat16* __restrict__ Al,
    const __nv_bfloat16* __restrict__ Bh, const __nv_bfloat16* __restrict__ Bl,
    int rowBase, int colBase, float (&acc)[4][4][4])
{
    extern __shared__ char smem[];
    const uint32_t sb = smem_u32(smem);
    const int tid  = threadIdx.x;
    const int wid  = tid >> 5, lane = tid & 31;
    const int wm   = wid >> 2, wn = wid & 3;
    const int lr   = lane & 15, lh = lane >> 4;

#pragma unroll
    for (int mi = 0; mi < 4; ++mi)
#pragma unroll
        for (int ni = 0; ni < 4; ++ni)
#pragma unroll
            for (int j = 0; j < 4; ++j) acc[mi][ni][j] = 0.0f;

    load_chunk(sb,         Ah, Al, Bh, Bl, rowBase, colBase, 0,  tid);
    CP_COMMIT();
    load_chunk(sb + STAGE, Ah, Al, Bh, Bl, rowBase, colBase, 32, tid);
    CP_COMMIT();

    for (int c = 0; c < NCH; ++c) {
        CP_WAIT1();
        __syncthreads();

        const uint32_t sbuf = sb + (uint32_t)(c & 1) * STAGE;
#pragma unroll
        for (int kh = 0; kh < 2; ++kh) {
            const int k16b = kh * 32;
            uint32_t bhf[2][4], blf[2][4];
#pragma unroll
            for (int nj = 0; nj < 2; ++nj) {
                const uint32_t baddr = sbuf + (uint32_t)(kh * 16 + lr) * 272
                                     + (uint32_t)(wn * 32 + nj * 16) * 2 + lh * 16;
                LDSM4T(bhf[nj], baddr + BH_OFF);
                LDSM4T(blf[nj], baddr + BL_OFF);
            }
#pragma unroll
            for (int mi = 0; mi < 4; ++mi) {
                uint32_t ah[4], al[4];
                const uint32_t raddr = sbuf + (uint32_t)(wm * 64 + mi * 16 + lr) * 80
                                     + k16b + lh * 16;
                LDSM4(ah, raddr + AH_OFF);
                LDSM4(al, raddr + AL_OFF);
#pragma unroll
                for (int ni = 0; ni < 4; ++ni) {
                    const int nj = ni >> 1, hp = (ni & 1) * 2;
                    MMA16816(acc[mi][ni], ah, bhf[nj][hp], bhf[nj][hp + 1]);
                }
#pragma unroll
                for (int ni = 0; ni < 4; ++ni) {
                    const int nj = ni >> 1, hp = (ni & 1) * 2;
                    MMA16816(acc[mi][ni], al, bhf[nj][hp], bhf[nj][hp + 1]);
                }
#pragma unroll
                for (int ni = 0; ni < 4; ++ni) {
                    const int nj = ni >> 1, hp = (ni & 1) * 2;
                    MMA16816(acc[mi][ni], ah, blf[nj][hp], blf[nj][hp + 1]);
                }
            }
        }
        __syncthreads();
        if (c + 2 < NCH)
            load_chunk(sb + (uint32_t)(c & 1) * STAGE, Ah, Al, Bh, Bl,
                       rowBase, colBase, (c + 2) * 32, tid);
        CP_COMMIT();
    }
}

// ---------------------------------------------------------------------------
// Q/K/V projection. z = blockIdx.z. Output head-split [B,H,S,64], Q x0.125.
// ---------------------------------------------------------------------------
struct BiasArgs { const float* bias[3]; };

__global__ __launch_bounds__(256, 2) void proj_mma_kernel(BiasArgs ba) {
    const int z = blockIdx.z;
    const int rowBase = blockIdx.y * 128;
    const int colBase = blockIdx.x * 128;

    float acc[4][4][4];
    gemm_core_mma(g_xh + (size_t)z * NSLOT, g_xl + (size_t)z * NSLOT,
                  g_wh + (size_t)z * WSLOT, g_wl + (size_t)z * WSLOT,
                  rowBase, colBase, acc);

    const int tid = threadIdx.x;
    const int wid = tid >> 5, lane = tid & 31;
    const int wm = wid >> 2, wn = wid & 3;
    const int g = lane >> 2, tq = lane & 3;

    float* dst = (z == 0) ? g_q : (z == 1) ? g_k : g_v;
    const float scale = (z == 0) ? 0.125f : 1.0f;
    const float* bias = ba.bias[z];

#pragma unroll
    for (int mi = 0; mi < 4; ++mi) {
        const int r0 = rowBase + wm * 64 + mi * 16 + g;
#pragma unroll
        for (int ni = 0; ni < 4; ++ni) {
            const int cc = colBase + wn * 32 + ni * 8 + tq * 2;
            const int h = cc >> 6, d = cc & 63;
            const float2 b2 = *(const float2*)(bias + cc);
            {
                const int r = r0, b = r >> 10, s = r & 1023;
                float* p = dst + ((size_t)((b * 8 + h) * 1024 + s)) * 64 + d;
                p[0] = (acc[mi][ni][0] + b2.x) * scale;
                p[1] = (acc[mi][ni][1] + b2.y) * scale;
            }
            {
                const int r = r0 + 8, b = r >> 10, s = r & 1023;
                float* p = dst + ((size_t)((b * 8 + h) * 1024 + s)) * 64 + d;
                p[0] = (acc[mi][ni][2] + b2.x) * scale;
                p[1] = (acc[mi][ni][3] + b2.y) * scale;
            }
        }
    }
}

// ---------------------------------------------------------------------------
// Final projection: d_out = (aoh+aol) @ Wo + bo
// ---------------------------------------------------------------------------
__global__ __launch_bounds__(256, 2) void out_mma_kernel(const float* __restrict__ bo,
                                                         float* __restrict__ out) {
    const int rowBase = blockIdx.y * 128;
    const int colBase = blockIdx.x * 128;

    float acc[4][4][4];
    gemm_core_mma(g_aoh, g_aol, g_wh + (size_t)3 * WSLOT, g_wl + (size_t)3 * WSLOT,
                  rowBase, colBase, acc);

    const int tid = threadIdx.x;
    const int wid = tid >> 5, lane = tid & 31;
    const int wm = wid >> 2, wn = wid & 3;
    const int g = lane >> 2, tq = lane & 3;

#pragma unroll
    for (int mi = 0; mi < 4; ++mi) {
        const int r0 = rowBase + wm * 64 + mi * 16 + g;
#pragma unroll
        for (int ni = 0; ni < 4; ++ni) {
            const int cc = colBase + wn * 32 + ni * 8 + tq * 2;
            const float2 b2 = *(const float2*)(bo + cc);
            {
                float* p = out + (size_t)r0 * D_ + cc;
                p[0] = acc[mi][ni][0] + b2.x;
                p[1] = acc[mi][ni][1] + b2.y;
            }
            {
                float* p = out + (size_t)(r0 + 8) * D_ + cc;
                p[0] = acc[mi][ni][2] + b2.x;
                p[1] = acc[mi][ni][3] + b2.y;
            }
        }
    }
}

// ---------------------------------------------------------------------------
// Sparse attention: one warp per (bh, query i); HALF-WARP per candidate.
// Register-trimmed: no jc[] array (j recomputed in the PV loop; invalid
// candidates carry weight exp->0 so a clamped row contributes exactly 0).
// __launch_bounds__(256,6) targets <=42 regs -> 6 CTAs/SM (75% occupancy)
// to hide the gathered K/V L1/L2 latency (kernel is L1-latency bound at 46%).
// ---------------------------------------------------------------------------
__global__ __launch_bounds__(256, 6) void attn_kernel() {
    const int gw   = (blockIdx.x * blockDim.x + threadIdx.x) >> 5;
    const int lane = threadIdx.x & 31;
    const int h2 = lane >> 4, sl = lane & 15;
    const int bh = gw >> 10;
    const int i  = gw & 1023;

    const float4* K4 = (const float4*)(g_k + (size_t)bh * (S_ * DH));
    const float4* V4 = (const float4*)(g_v + (size_t)bh * (S_ * DH));
    const float4 q = ((const float4*)(g_q + (size_t)gw * 64))[sl];

    const int t  = i >> 8;
    const int hh = (i >> 4) & 15;

    float lg[17];
#pragma unroll
    for (int it = 0; it < 17; ++it) {
        const int c = it * 2 + h2;
        int j; bool valid;
        if (c < 17)      { j = i - 16 + c;              valid = (j >= 0); }
        else if (c < 31) { const int kk = c - 15; j = i - (kk << 4); valid = (kk <= hh); }
        else             { const int kk = c - 30; j = i - (kk << 8); valid = (kk <= t); }
        const int ja = valid ? j : i;
        const float4 kv = K4[ja * 16 + sl];
        float p = q.x * kv.x + q.y * kv.y + q.z * kv.z + q.w * kv.w;
        p += __shfl_xor_sync(0xffffffffu, p, 8);
        p += __shfl_xor_sync(0xffffffffu, p, 4);
        p += __shfl_xor_sync(0xffffffffu, p, 2);
        p += __shfl_xor_sync(0xffffffffu, p, 1);
        lg[it] = valid ? p : -1e30f;
    }

    float mx = -1e30f;
#pragma unroll
    for (int it = 0; it < 17; ++it) mx = fmaxf(mx, lg[it]);
    mx = fmaxf(mx, __shfl_xor_sync(0xffffffffu, mx, 16));

    float s = 0.0f;
#pragma unroll
    for (int it = 0; it < 17; ++it) {
        const float e = __expf(lg[it] - mx);   // invalid underflows to exactly 0
        lg[it] = e;
        s += e;
    }
    s += __shfl_xor_sync(0xffffffffu, s, 16);

    float4 o = make_float4(0.f, 0.f, 0.f, 0.f);
#pragma unroll
    for (int it = 0; it < 17; ++it) {
        const int c = it * 2 + h2;
        int j;
        if (c < 17)      j = i - 16 + c;
        else if (c < 31) j = i - ((c - 15) << 4);
        else             j = i - ((c - 30) << 8);
        j = j < 0 ? 0 : j;                 // weight is 0 whenever clamped/invalid
        const float4 v = V4[j * 16 + sl];
        const float w = lg[it];
        o.x = fmaf(w, v.x, o.x);
        o.y = fmaf(w, v.y, o.y);
        o.z = fmaf(w, v.z, o.z);
        o.w = fmaf(w, v.w, o.w);
    }
    o.x += __shfl_xor_sync(0xffffffffu, o.x, 16);
    o.y += __shfl_xor_sync(0xffffffffu, o.y, 16);
    o.z += __shfl_xor_sync(0xffffffffu, o.z, 16);
    o.w += __shfl_xor_sync(0xffffffffu, o.w, 16);

    const float inv = 1.0f / s;
    o.x *= inv; o.y *= inv; o.z *= inv; o.w *= inv;

    // split to bf16 hi/lo; half 0 writes hi, half 1 writes lo
    uint32_t h01, h23, l01, l23;
    split4(o, h01, h23, l01, l23);
    const int b = bh >> 3, h = bh & 7;
    const size_t off = ((size_t)((b << 10) + i)) * 512 + (h << 6) + sl * 4;
    if (h2 == 0) *(uint2*)(g_aoh + off) = make_uint2(h01, h23);
    else         *(uint2*)(g_aol + off) = make_uint2(l01, l23);
}

// ---------------------------------------------------------------------------
extern "C" void kernel_launch(void* const* d_in, const int* in_sizes, int n_in,
                              void* d_out, int out_size) {
    const float* query = (const float*)d_in[0];
    const float* key   = (const float*)d_in[1];
    const float* value = (const float*)d_in[2];
    const float* Wq    = (const float*)d_in[3];
    const float* bq    = (const float*)d_in[4];
    const float* Wk    = (const float*)d_in[5];
    const float* bk    = (const float*)d_in[6];
    const float* Wv    = (const float*)d_in[7];
    const float* bv    = (const float*)d_in[8];
    const float* Wo    = (const float*)d_in[9];
    const float* bo    = (const float*)d_in[10];

    cudaFuncSetAttribute(proj_mma_kernel,
                         cudaFuncAttributeMaxDynamicSharedMemorySize, SMEM_TOTAL);
    cudaFuncSetAttribute(out_mma_kernel,
                         cudaFuncAttributeMaxDynamicSharedMemorySize, SMEM_TOTAL);

    WArgs wa; wa.W[0] = Wq; wa.W[1] = Wk; wa.W[2] = Wv; wa.W[3] = Wo;
    prep_w_kernel<<<dim3(256, 4), 256>>>(wa);

    XArgs xa; xa.X[0] = query; xa.X[1] = key; xa.X[2] = value;
    prep_x_kernel<<<dim3(4096, 3), 256>>>(xa);

    BiasArgs ba; ba.bias[0] = bq; ba.bias[1] = bk; ba.bias[2] = bv;
    proj_mma_kernel<<<dim3(4, 64, 3), 256, SMEM_TOTAL>>>(ba);

    attn_kernel<<<(B_ * H_ * S_ * 32) / 256, 256>>>();

    out_mma_kernel<<<dim3(4, 64, 1), 256, SMEM_TOTAL>>>(bo, (float*)d_out);
}

// round 16
// speedup vs baseline: 1.1565x; 1.1506x over previous
#include <cuda_runtime.h>
#include <cstdint>

// ---------------- problem constants ----------------
#define B_   8
#define H_   8
#define S_   1024
#define DH   64
#define D_   512
#define MR   8192                // B_*S_
#define NCH  16                  // 512 / 32
#define NSLOT (MR * D_)          // 4194304 activation elems
#define WSLOT (D_ * D_)          // 262144 weight elems

// ---------------- scratch (device globals; no allocation allowed) ---------
__device__ float g_q[B_ * H_ * S_ * DH];   // [BH,S,64], pre-scaled by 0.125
__device__ float g_k[B_ * H_ * S_ * DH];
__device__ float g_v[B_ * H_ * S_ * DH];
__device__ __align__(128) float g_x32[3 * NSLOT];  // tf32-rounded query,key,value
__device__ __align__(128) float g_w32[4 * WSLOT];  // tf32-rounded Wq,Wk,Wv,Wo ([k][n])
__device__ __align__(128) float g_ao[NSLOT];       // attn out (tf32-rounded) [B*S,512]

// ---------------- SMEM layout (bytes, per stage) ----------------
// A: 128 rows x 144B (32 fp32 + 16B pad)   = 18432  (bank bijection: 36 % 32 = 4)
// B: 32 k-rows x 544B (128 fp32 + 32B pad) = 17408  (136 % 32 = 8)
#define A_OFF   0
#define B_OFF   18432
#define STAGE   35840
#define SMEM_TOTAL (2 * STAGE)   // 71680 -> 2 CTAs/SM

__device__ __forceinline__ uint32_t smem_u32(const void* p) {
    uint32_t a;
    asm("{ .reg .u64 t; cvta.to.shared.u64 t, %1; cvt.u32.u64 %0, t; }" : "=r"(a) : "l"(p));
    return a;
}

#define CP16(dst, src) \
    asm volatile("cp.async.cg.shared.global [%0], [%1], 16;" :: "r"(dst), "l"(src))
#define CP_COMMIT() asm volatile("cp.async.commit_group;" ::: "memory")
#define CP_WAIT1()  asm volatile("cp.async.wait_group 1;" ::: "memory")

// tf32 MMA: D[16x8] += A[16x8] * B[8x8]; A row-major frag (4 regs), B col frag (2 regs)
#define MMAT32(c, a0, a1, a2, a3, b0, b1) \
    asm volatile("mma.sync.aligned.m16n8k8.row.col.f32.tf32.tf32.f32 " \
        "{%0,%1,%2,%3}, {%4,%5,%6,%7}, {%8,%9}, {%0,%1,%2,%3};" \
        : "+f"((c)[0]), "+f"((c)[1]), "+f"((c)[2]), "+f"((c)[3]) \
        : "r"(a0), "r"(a1), "r"(a2), "r"(a3), "r"(b0), "r"(b1))

__device__ __forceinline__ float tf32r(float x) {
    uint32_t y;
    asm("cvt.rna.tf32.f32 %0, %1;" : "=r"(y) : "f"(x));
    return __uint_as_float(y);
}

// ---------------------------------------------------------------------------
// prep kernels: round fp32 tensors to tf32 (rna) once per launch.
// ---------------------------------------------------------------------------
struct XArgs { const float* X[3]; };
struct WArgs { const float* W[4]; };

__global__ __launch_bounds__(256) void prep_x_kernel(XArgs xa) {
    const int z = blockIdx.y;
    const size_t i = (size_t)blockIdx.x * 256 + threadIdx.x;   // float4 idx
    float4 v = ((const float4*)xa.X[z])[i];
    v.x = tf32r(v.x); v.y = tf32r(v.y); v.z = tf32r(v.z); v.w = tf32r(v.w);
    ((float4*)(g_x32 + (size_t)z * NSLOT))[i] = v;
}

__global__ __launch_bounds__(256) void prep_w_kernel(WArgs wa) {
    const int z = blockIdx.y;
    const size_t i = (size_t)blockIdx.x * 256 + threadIdx.x;
    float4 v = ((const float4*)wa.W[z])[i];
    v.x = tf32r(v.x); v.y = tf32r(v.y); v.z = tf32r(v.z); v.w = tf32r(v.w);
    ((float4*)(g_w32 + (size_t)z * WSLOT))[i] = v;
}

// ---------------------------------------------------------------------------
// cp.async chunk loader: A[128 x 32] fp32 + B[32 x 128] fp32
// ---------------------------------------------------------------------------
__device__ __forceinline__ void load_chunk(
    uint32_t sdst, const float* __restrict__ A, const float* __restrict__ W,
    int rowBase, int colBase, int k0, int tid)
{
#pragma unroll
    for (int i = 0; i < 4; ++i) {
        const int idx = i * 256 + tid;
        // A: 1024 granules, 8 per 128B row
        const int row = idx >> 3, c4 = idx & 7;
        CP16(sdst + A_OFF + row * 144 + c4 * 16,
             A + (size_t)(rowBase + row) * D_ + k0 + c4 * 4);
    }
#pragma unroll
    for (int i = 0; i < 4; ++i) {
        const int idx = i * 256 + tid;
        // B: 1024 granules, 32 per 512B row
        const int row = idx >> 5, cc = idx & 31;
        CP16(sdst + B_OFF + row * 544 + cc * 16,
             W + (size_t)(k0 + row) * D_ + colBase + cc * 4);
    }
}

// ---------------------------------------------------------------------------
// Single-pass TF32 GEMM core, 2-stage cp.async pipeline.
// CTA tile 128(m) x 128(n), 8 warps of 64(m) x 32(n); per chunk 4 k8-steps.
//   acc = A[rowBase:+128, :512] @ W[:512, colBase:+128]   (tf32-rounded fp32)
// A frags via conflict-free LDS.32 (row stride 36 fl: bank = 4g+tq bijection),
// B frags likewise (row stride 136 fl: bank = 8k+n bijection).
// Accumulator layout identical to m16n8k16 -> epilogues unchanged.
// ---------------------------------------------------------------------------
__device__ __forceinline__ void gemm_core_tf32(
    const float* __restrict__ A, const float* __restrict__ W,
    int rowBase, int colBase, float (&acc)[4][4][4])
{
    extern __shared__ char smem[];
    const uint32_t sb = smem_u32(smem);
    const int tid  = threadIdx.x;
    const int wid  = tid >> 5, lane = tid & 31;
    const int wm   = wid >> 2, wn = wid & 3;
    const int g    = lane >> 2, tq = lane & 3;

#pragma unroll
    for (int mi = 0; mi < 4; ++mi)
#pragma unroll
        for (int ni = 0; ni < 4; ++ni)
#pragma unroll
            for (int j = 0; j < 4; ++j) acc[mi][ni][j] = 0.0f;

    load_chunk(sb,         A, W, rowBase, colBase, 0,  tid);
    CP_COMMIT();
    load_chunk(sb + STAGE, A, W, rowBase, colBase, 32, tid);
    CP_COMMIT();

    for (int c = 0; c < NCH; ++c) {
        CP_WAIT1();
        __syncthreads();

        const char* sbase = smem + (size_t)(c & 1) * STAGE;
        const uint32_t* As = (const uint32_t*)(sbase + A_OFF);
        const uint32_t* Bs = (const uint32_t*)(sbase + B_OFF);

#pragma unroll
        for (int s = 0; s < 4; ++s) {
            const int kb = tq + s * 8;
            uint32_t b0[4], b1[4];
#pragma unroll
            for (int nj = 0; nj < 4; ++nj) {
                const int nb = wn * 32 + nj * 8 + g;
                b0[nj] = Bs[kb * 136 + nb];
                b1[nj] = Bs[(kb + 4) * 136 + nb];
            }
#pragma unroll
            for (int mi = 0; mi < 4; ++mi) {
                const int ra = wm * 64 + mi * 16 + g;
                const int ca = tq + s * 8;
                const uint32_t a0 = As[ra * 36 + ca];
                const uint32_t a1 = As[(ra + 8) * 36 + ca];
                const uint32_t a2 = As[ra * 36 + ca + 4];
                const uint32_t a3 = As[(ra + 8) * 36 + ca + 4];
#pragma unroll
                for (int ni = 0; ni < 4; ++ni)
                    MMAT32(acc[mi][ni], a0, a1, a2, a3, b0[ni], b1[ni]);
            }
        }
        __syncthreads();
        if (c + 2 < NCH)
            load_chunk(sb + (uint32_t)(c & 1) * STAGE, A, W,
                       rowBase, colBase, (c + 2) * 32, tid);
        CP_COMMIT();
    }
}

// ---------------------------------------------------------------------------
// Q/K/V projection. z = blockIdx.z. Output head-split [B,H,S,64], Q x0.125.
// ---------------------------------------------------------------------------
struct BiasArgs { const float* bias[3]; };

__global__ __launch_bounds__(256, 2) void proj_mma_kernel(BiasArgs ba) {
    const int z = blockIdx.z;
    const int rowBase = blockIdx.y * 128;
    const int colBase = blockIdx.x * 128;

    float acc[4][4][4];
    gemm_core_tf32(g_x32 + (size_t)z * NSLOT, g_w32 + (size_t)z * WSLOT,
                   rowBase, colBase, acc);

    const int tid = threadIdx.x;
    const int wid = tid >> 5, lane = tid & 31;
    const int wm = wid >> 2, wn = wid & 3;
    const int g = lane >> 2, tq = lane & 3;

    float* dst = (z == 0) ? g_q : (z == 1) ? g_k : g_v;
    const float scale = (z == 0) ? 0.125f : 1.0f;
    const float* bias = ba.bias[z];

#pragma unroll
    for (int mi = 0; mi < 4; ++mi) {
        const int r0 = rowBase + wm * 64 + mi * 16 + g;
#pragma unroll
        for (int ni = 0; ni < 4; ++ni) {
            const int cc = colBase + wn * 32 + ni * 8 + tq * 2;
            const int h = cc >> 6, d = cc & 63;
            const float2 b2 = *(const float2*)(bias + cc);
            {
                const int r = r0, b = r >> 10, s = r & 1023;
                float* p = dst + ((size_t)((b * 8 + h) * 1024 + s)) * 64 + d;
                p[0] = (acc[mi][ni][0] + b2.x) * scale;
                p[1] = (acc[mi][ni][1] + b2.y) * scale;
            }
            {
                const int r = r0 + 8, b = r >> 10, s = r & 1023;
                float* p = dst + ((size_t)((b * 8 + h) * 1024 + s)) * 64 + d;
                p[0] = (acc[mi][ni][2] + b2.x) * scale;
                p[1] = (acc[mi][ni][3] + b2.y) * scale;
            }
        }
    }
}

// ---------------------------------------------------------------------------
// Final projection: d_out = g_ao @ Wo + bo
// ---------------------------------------------------------------------------
__global__ __launch_bounds__(256, 2) void out_mma_kernel(const float* __restrict__ bo,
                                                         float* __restrict__ out) {
    const int rowBase = blockIdx.y * 128;
    const int colBase = blockIdx.x * 128;

    float acc[4][4][4];
    gemm_core_tf32(g_ao, g_w32 + (size_t)3 * WSLOT, rowBase, colBase, acc);

    const int tid = threadIdx.x;
    const int wid = tid >> 5, lane = tid & 31;
    const int wm = wid >> 2, wn = wid & 3;
    const int g = lane >> 2, tq = lane & 3;

#pragma unroll
    for (int mi = 0; mi < 4; ++mi) {
        const int r0 = rowBase + wm * 64 + mi * 16 + g;
#pragma unroll
        for (int ni = 0; ni < 4; ++ni) {
            const int cc = colBase + wn * 32 + ni * 8 + tq * 2;
            const float2 b2 = *(const float2*)(bo + cc);
            {
                float* p = out + (size_t)r0 * D_ + cc;
                p[0] = acc[mi][ni][0] + b2.x;
                p[1] = acc[mi][ni][1] + b2.y;
            }
            {
                float* p = out + (size_t)(r0 + 8) * D_ + cc;
                p[0] = acc[mi][ni][2] + b2.x;
                p[1] = acc[mi][ni][3] + b2.y;
            }
        }
    }
}

// ---------------------------------------------------------------------------
// Sparse attention (R4-proven body): one warp per (bh, query i); HALF-WARP per
// candidate. 34 candidates = 17 iterations x 2 halves. float4 over head dim.
// Epilogue: tf32-round and store fp32 g_ao directly (h2==0 half writes).
// ---------------------------------------------------------------------------
__global__ __launch_bounds__(256) void attn_kernel() {
    const int gw   = (blockIdx.x * blockDim.x + threadIdx.x) >> 5;
    const int lane = threadIdx.x & 31;
    const int h2 = lane >> 4, sl = lane & 15;
    const int bh = gw >> 10;
    const int i  = gw & 1023;

    const float4* K4 = (const float4*)(g_k + (size_t)bh * (S_ * DH));
    const float4* V4 = (const float4*)(g_v + (size_t)bh * (S_ * DH));
    const float4 q = ((const float4*)(g_q + (size_t)gw * 64))[sl];

    const int t  = i >> 8;
    const int hh = (i >> 4) & 15;

    float lg[17];
    int   jc[17];
#pragma unroll
    for (int it = 0; it < 17; ++it) {
        const int c = it * 2 + h2;
        int j; bool valid;
        if (c < 17)      { j = i - 16 + c;              valid = (j >= 0); }
        else if (c < 31) { const int kk = c - 15; j = i - (kk << 4); valid = (kk <= hh); }
        else             { const int kk = c - 30; j = i - (kk << 8); valid = (kk <= t); }
        jc[it] = valid ? j : i;           // clamp to self row; masked below
        const float4 kv = K4[jc[it] * 16 + sl];
        float p = q.x * kv.x + q.y * kv.y + q.z * kv.z + q.w * kv.w;
        p += __shfl_xor_sync(0xffffffffu, p, 8);
        p += __shfl_xor_sync(0xffffffffu, p, 4);
        p += __shfl_xor_sync(0xffffffffu, p, 2);
        p += __shfl_xor_sync(0xffffffffu, p, 1);
        lg[it] = valid ? p : -1e30f;
    }

    float mx = -1e30f;
#pragma unroll
    for (int it = 0; it < 17; ++it) mx = fmaxf(mx, lg[it]);
    mx = fmaxf(mx, __shfl_xor_sync(0xffffffffu, mx, 16));

    float s = 0.0f;
#pragma unroll
    for (int it = 0; it < 17; ++it) {
        const float e = __expf(lg[it] - mx);   // invalid underflows to 0
        lg[it] = e;
        s += e;
    }
    s += __shfl_xor_sync(0xffffffffu, s, 16);

    float4 o = make_float4(0.f, 0.f, 0.f, 0.f);
#pragma unroll
    for (int it = 0; it < 17; ++it) {
        const float4 v = V4[jc[it] * 16 + sl];
        const float w = lg[it];
        o.x = fmaf(w, v.x, o.x);
        o.y = fmaf(w, v.y, o.y);
        o.z = fmaf(w, v.z, o.z);
        o.w = fmaf(w, v.w, o.w);
    }
    o.x += __shfl_xor_sync(0xffffffffu, o.x, 16);
    o.y += __shfl_xor_sync(0xffffffffu, o.y, 16);
    o.z += __shfl_xor_sync(0xffffffffu, o.z, 16);
    o.w += __shfl_xor_sync(0xffffffffu, o.w, 16);

    if (h2 == 0) {
        const float inv = 1.0f / s;
        float4 r;
        r.x = tf32r(o.x * inv);
        r.y = tf32r(o.y * inv);
        r.z = tf32r(o.z * inv);
        r.w = tf32r(o.w * inv);
        const int b = bh >> 3, h = bh & 7;
        const size_t off = ((size_t)((b << 10) + i)) * 512 + (h << 6) + sl * 4;
        *(float4*)(g_ao + off) = r;
    }
}

// ---------------------------------------------------------------------------
extern "C" void kernel_launch(void* const* d_in, const int* in_sizes, int n_in,
                              void* d_out, int out_size) {
    const float* query = (const float*)d_in[0];
    const float* key   = (const float*)d_in[1];
    const float* value = (const float*)d_in[2];
    const float* Wq    = (const float*)d_in[3];
    const float* bq    = (const float*)d_in[4];
    const float* Wk    = (const float*)d_in[5];
    const float* bk    = (const float*)d_in[6];
    const float* Wv    = (const float*)d_in[7];
    const float* bv    = (const float*)d_in[8];
    const float* Wo    = (const float*)d_in[9];
    const float* bo    = (const float*)d_in[10];

    cudaFuncSetAttribute(proj_mma_kernel,
                         cudaFuncAttributeMaxDynamicSharedMemorySize, SMEM_TOTAL);
    cudaFuncSetAttribute(out_mma_kernel,
                         cudaFuncAttributeMaxDynamicSharedMemorySize, SMEM_TOTAL);

    WArgs wa; wa.W[0] = Wq; wa.W[1] = Wk; wa.W[2] = Wv; wa.W[3] = Wo;
    prep_w_kernel<<<dim3(256, 4), 256>>>(wa);

    XArgs xa; xa.X[0] = query; xa.X[1] = key; xa.X[2] = value;
    prep_x_kernel<<<dim3(4096, 3), 256>>>(xa);

    BiasArgs ba; ba.bias[0] = bq; ba.bias[1] = bk; ba.bias[2] = bv;
    proj_mma_kernel<<<dim3(4, 64, 3), 256, SMEM_TOTAL>>>(ba);

    attn_kernel<<<(B_ * H_ * S_ * 32) / 256, 256>>>();

    out_mma_kernel<<<dim3(4, 64, 1), 256, SMEM_TOTAL>>>(bo, (float*)d_out);
}